// round 2
// baseline (speedup 1.0000x reference)
#include <cuda_runtime.h>
#include <cuda_bf16.h>

// DropNorm: per-row masked mean/var (unbiased), normalize masked elems,
// scatter (zeros elsewhere), affine. Quirk preserved: rsqrt(sigma2^2 + eps).
//
// B=4096 rows, F=8192 features. One CTA per row; row cached in smem so x is
// read from HBM exactly once. Single-pass sums: Σ(x-mu)^2*m = Σx^2 m - n mu^2.
// Mask arrives as int32 (bool promoted by the harness).

constexpr int F_DIM   = 8192;
constexpr int BLOCK   = 512;
constexpr int VEC     = F_DIM / 4;       // 2048 float4 per row
constexpr int ITERS   = VEC / BLOCK;     // 4
constexpr float EPS   = 1e-4f;

__global__ __launch_bounds__(BLOCK, 4) void dropnorm_kernel(
    const float* __restrict__ x,
    const float* __restrict__ gamma,
    const float* __restrict__ beta,
    const int*   __restrict__ mask,
    float* __restrict__ out)
{
    __shared__ float4 sx[VEC];                 // 32 KB row cache
    __shared__ float  red_s [BLOCK / 32];
    __shared__ float  red_ss[BLOCK / 32];
    __shared__ float  s_mu, s_inv;

    const int row = blockIdx.x;
    const float4* __restrict__ xrow =
        reinterpret_cast<const float4*>(x) + (size_t)row * VEC;
    const int4* __restrict__ m4 = reinterpret_cast<const int4*>(mask);

    // ---- Pass 1: load row (HBM once), stash in smem, accumulate Σxm, Σx²m ----
    float s = 0.f, ss = 0.f;
#pragma unroll
    for (int i = 0; i < ITERS; ++i) {
        const int idx = threadIdx.x + i * BLOCK;
        const float4 v  = xrow[idx];
        sx[idx] = v;
        const int4 mm = m4[idx];
        if (mm.x) { s += v.x; ss = fmaf(v.x, v.x, ss); }
        if (mm.y) { s += v.y; ss = fmaf(v.y, v.y, ss); }
        if (mm.z) { s += v.z; ss = fmaf(v.z, v.z, ss); }
        if (mm.w) { s += v.w; ss = fmaf(v.w, v.w, ss); }
    }

    // ---- Block reduction of (s, ss) ----
#pragma unroll
    for (int off = 16; off > 0; off >>= 1) {
        s  += __shfl_xor_sync(0xFFFFFFFFu, s,  off);
        ss += __shfl_xor_sync(0xFFFFFFFFu, ss, off);
    }
    const int lane = threadIdx.x & 31;
    const int wid  = threadIdx.x >> 5;
    if (lane == 0) { red_s[wid] = s; red_ss[wid] = ss; }
    __syncthreads();
    if (wid == 0) {
        constexpr int NW = BLOCK / 32;  // 16
        s  = (lane < NW) ? red_s [lane] : 0.f;
        ss = (lane < NW) ? red_ss[lane] : 0.f;
#pragma unroll
        for (int off = NW / 2; off > 0; off >>= 1) {
            s  += __shfl_xor_sync(0xFFFFFFFFu, s,  off);
            ss += __shfl_xor_sync(0xFFFFFFFFu, ss, off);
        }
        if (lane == 0) {
            const float n  = (float)(F_DIM / 2);          // 4096 masked elems
            const float mu = s / n;
            const float sigma2 = (ss - n * mu * mu) / (n - 1.f);
            s_mu  = mu;
            // reference quirk: sigma2 SQUARED inside the sqrt
            s_inv = rsqrtf(fmaf(sigma2, sigma2, EPS));
        }
    }
    __syncthreads();

    const float mu  = s_mu;
    const float inv = s_inv;

    // ---- Pass 2: normalize + affine from smem, write out (HBM once) ----
    const float4* __restrict__ g4 = reinterpret_cast<const float4*>(gamma);
    const float4* __restrict__ b4 = reinterpret_cast<const float4*>(beta);
    float4* __restrict__ orow =
        reinterpret_cast<float4*>(out) + (size_t)row * VEC;
#pragma unroll
    for (int i = 0; i < ITERS; ++i) {
        const int idx = threadIdx.x + i * BLOCK;
        const float4 v  = sx[idx];
        const int4  mm = m4[idx];
        const float4 g  = g4[idx];
        const float4 bb = b4[idx];
        float4 o;
        o.x = mm.x ? fmaf(g.x, (v.x - mu) * inv, bb.x) : bb.x;
        o.y = mm.y ? fmaf(g.y, (v.y - mu) * inv, bb.y) : bb.y;
        o.z = mm.z ? fmaf(g.z, (v.z - mu) * inv, bb.z) : bb.z;
        o.w = mm.w ? fmaf(g.w, (v.w - mu) * inv, bb.w) : bb.w;
        orow[idx] = o;
    }
}

extern "C" void kernel_launch(void* const* d_in, const int* in_sizes, int n_in,
                              void* d_out, int out_size)
{
    const float* x     = (const float*)d_in[0];
    const float* gamma = (const float*)d_in[1];
    const float* beta  = (const float*)d_in[2];
    const int*   mask  = (const int*)d_in[3];
    float*       out   = (float*)d_out;

    const int B = in_sizes[0] / F_DIM;   // 4096
    dropnorm_kernel<<<B, BLOCK>>>(x, gamma, beta, mask, out);
}

// round 5
// speedup vs baseline: 1.0769x; 1.0769x over previous
#include <cuda_runtime.h>
#include <cuda_bf16.h>

// DropNorm: per-row masked mean/var (unbiased), normalize masked elems,
// scatter (zeros elsewhere), affine. Quirk preserved: rsqrt(sigma2^2 + eps).
//
// R3: x held in REGISTERS across the reduction (no smem row cache), mask
// packed to predicate bits in pass 1. Cuts per-CTA L1 traffic 256KB -> 160KB
// (smem round-trip + duplicate mask load eliminated). DRAM becomes the limit.

constexpr int F_DIM   = 8192;
constexpr int BLOCK   = 512;
constexpr int VEC     = F_DIM / 4;       // 2048 float4 per row
constexpr int ITERS   = VEC / BLOCK;     // 4
constexpr float EPS   = 1e-4f;

__global__ __launch_bounds__(BLOCK, 2) void dropnorm_kernel(
    const float* __restrict__ x,
    const float* __restrict__ gamma,
    const float* __restrict__ beta,
    const int*   __restrict__ mask,
    float* __restrict__ out)
{
    __shared__ float red_s [BLOCK / 32];
    __shared__ float red_ss[BLOCK / 32];
    __shared__ float s_mu, s_inv;

    const int row = blockIdx.x;
    const float4* __restrict__ xrow =
        reinterpret_cast<const float4*>(x) + (size_t)row * VEC;
    const int4* __restrict__ m4 = reinterpret_cast<const int4*>(mask);

    // ---- Pass 1: load row into REGISTERS, accumulate Σxm, Σx²m, pack mask ----
    float4 v[ITERS];
    unsigned mbits = 0;
    float s = 0.f, ss = 0.f;
#pragma unroll
    for (int i = 0; i < ITERS; ++i) {
        const int idx = threadIdx.x + i * BLOCK;
        v[i] = xrow[idx];
        const int4 mm = m4[idx];
        if (mm.x) { s += v[i].x; ss = fmaf(v[i].x, v[i].x, ss); mbits |= 1u << (4*i + 0); }
        if (mm.y) { s += v[i].y; ss = fmaf(v[i].y, v[i].y, ss); mbits |= 1u << (4*i + 1); }
        if (mm.z) { s += v[i].z; ss = fmaf(v[i].z, v[i].z, ss); mbits |= 1u << (4*i + 2); }
        if (mm.w) { s += v[i].w; ss = fmaf(v[i].w, v[i].w, ss); mbits |= 1u << (4*i + 3); }
    }

    // ---- Block reduction of (s, ss) ----
#pragma unroll
    for (int off = 16; off > 0; off >>= 1) {
        s  += __shfl_xor_sync(0xFFFFFFFFu, s,  off);
        ss += __shfl_xor_sync(0xFFFFFFFFu, ss, off);
    }
    const int lane = threadIdx.x & 31;
    const int wid  = threadIdx.x >> 5;
    if (lane == 0) { red_s[wid] = s; red_ss[wid] = ss; }
    __syncthreads();
    if (wid == 0) {
        constexpr int NW = BLOCK / 32;  // 16
        s  = (lane < NW) ? red_s [lane] : 0.f;
        ss = (lane < NW) ? red_ss[lane] : 0.f;
#pragma unroll
        for (int off = NW / 2; off > 0; off >>= 1) {
            s  += __shfl_xor_sync(0xFFFFFFFFu, s,  off);
            ss += __shfl_xor_sync(0xFFFFFFFFu, ss, off);
        }
        if (lane == 0) {
            const float n  = (float)(F_DIM / 2);          // 4096 masked elems
            const float mu = s / n;
            const float sigma2 = (ss - n * mu * mu) / (n - 1.f);
            s_mu  = mu;
            // reference quirk: sigma2 SQUARED inside the sqrt
            s_inv = rsqrtf(fmaf(sigma2, sigma2, EPS));
        }
    }
    __syncthreads();

    const float mu  = s_mu;
    const float inv = s_inv;

    // ---- Pass 2: normalize + affine from registers, write out ----
    const float4* __restrict__ g4 = reinterpret_cast<const float4*>(gamma);
    const float4* __restrict__ b4 = reinterpret_cast<const float4*>(beta);
    float4* __restrict__ orow =
        reinterpret_cast<float4*>(out) + (size_t)row * VEC;
#pragma unroll
    for (int i = 0; i < ITERS; ++i) {
        const int idx = threadIdx.x + i * BLOCK;
        const float4 g  = g4[idx];
        const float4 bb = b4[idx];
        float4 o;
        o.x = (mbits >> (4*i + 0)) & 1u ? fmaf(g.x, (v[i].x - mu) * inv, bb.x) : bb.x;
        o.y = (mbits >> (4*i + 1)) & 1u ? fmaf(g.y, (v[i].y - mu) * inv, bb.y) : bb.y;
        o.z = (mbits >> (4*i + 2)) & 1u ? fmaf(g.z, (v[i].z - mu) * inv, bb.z) : bb.z;
        o.w = (mbits >> (4*i + 3)) & 1u ? fmaf(g.w, (v[i].w - mu) * inv, bb.w) : bb.w;
        orow[idx] = o;
    }
}

extern "C" void kernel_launch(void* const* d_in, const int* in_sizes, int n_in,
                              void* d_out, int out_size)
{
    const float* x     = (const float*)d_in[0];
    const float* gamma = (const float*)d_in[1];
    const float* beta  = (const float*)d_in[2];
    const int*   mask  = (const int*)d_in[3];
    float*       out   = (float*)d_out;

    const int B = in_sizes[0] / F_DIM;   // 4096
    dropnorm_kernel<<<B, BLOCK>>>(x, gamma, beta, mask, out);
}

// round 8
// speedup vs baseline: 1.2050x; 1.1190x over previous
#include <cuda_runtime.h>
#include <cuda_bf16.h>

// DropNorm: per-row masked mean/var (unbiased), normalize masked elems,
// scatter (zeros elsewhere), affine. Quirk preserved: rsqrt(sigma2^2 + eps).
//
// R4: pass 2 re-loads x from L2 (row is hot; zero extra DRAM traffic) instead
// of holding it in registers. Frees ~20 regs -> 3 CTAs/SM (48 warps), hiding
// the per-CTA reduction/barrier dead time behind other CTAs' load streams.
// Output stored with .cs (streaming) to avoid evicting hot x rows from L2.

constexpr int F_DIM   = 8192;
constexpr int BLOCK   = 512;
constexpr int VEC     = F_DIM / 4;       // 2048 float4 per row
constexpr int ITERS   = VEC / BLOCK;     // 4
constexpr float EPS   = 1e-4f;

__global__ __launch_bounds__(BLOCK, 3) void dropnorm_kernel(
    const float* __restrict__ x,
    const float* __restrict__ gamma,
    const float* __restrict__ beta,
    const int*   __restrict__ mask,
    float* __restrict__ out)
{
    __shared__ float red_s [BLOCK / 32];
    __shared__ float red_ss[BLOCK / 32];
    __shared__ float s_mu, s_inv;

    const int row = blockIdx.x;
    const float4* __restrict__ xrow =
        reinterpret_cast<const float4*>(x) + (size_t)row * VEC;
    const int4* __restrict__ m4 = reinterpret_cast<const int4*>(mask);

    // ---- Pass 1: stream row, accumulate Σxm, Σx²m, pack mask bits ----
    unsigned mbits = 0;
    float s = 0.f, ss = 0.f;
#pragma unroll
    for (int i = 0; i < ITERS; ++i) {
        const int idx = threadIdx.x + i * BLOCK;
        const float4 v  = xrow[idx];
        const int4   mm = m4[idx];
        if (mm.x) { s += v.x; ss = fmaf(v.x, v.x, ss); mbits |= 1u << (4*i + 0); }
        if (mm.y) { s += v.y; ss = fmaf(v.y, v.y, ss); mbits |= 1u << (4*i + 1); }
        if (mm.z) { s += v.z; ss = fmaf(v.z, v.z, ss); mbits |= 1u << (4*i + 2); }
        if (mm.w) { s += v.w; ss = fmaf(v.w, v.w, ss); mbits |= 1u << (4*i + 3); }
    }

    // ---- Block reduction of (s, ss) ----
#pragma unroll
    for (int off = 16; off > 0; off >>= 1) {
        s  += __shfl_xor_sync(0xFFFFFFFFu, s,  off);
        ss += __shfl_xor_sync(0xFFFFFFFFu, ss, off);
    }
    const int lane = threadIdx.x & 31;
    const int wid  = threadIdx.x >> 5;
    if (lane == 0) { red_s[wid] = s; red_ss[wid] = ss; }
    __syncthreads();
    if (wid == 0) {
        constexpr int NW = BLOCK / 32;  // 16
        s  = (lane < NW) ? red_s [lane] : 0.f;
        ss = (lane < NW) ? red_ss[lane] : 0.f;
#pragma unroll
        for (int off = NW / 2; off > 0; off >>= 1) {
            s  += __shfl_xor_sync(0xFFFFFFFFu, s,  off);
            ss += __shfl_xor_sync(0xFFFFFFFFu, ss, off);
        }
        if (lane == 0) {
            const float n  = (float)(F_DIM / 2);          // 4096 masked elems
            const float mu = s / n;
            const float sigma2 = (ss - n * mu * mu) / (n - 1.f);
            s_mu  = mu;
            // reference quirk: sigma2 SQUARED inside the sqrt
            s_inv = rsqrtf(fmaf(sigma2, sigma2, EPS));
        }
    }
    __syncthreads();

    const float mu  = s_mu;
    const float inv = s_inv;

    // ---- Pass 2: re-load x (L2 hit), normalize + affine, streaming store ----
    const float4* __restrict__ g4 = reinterpret_cast<const float4*>(gamma);
    const float4* __restrict__ b4 = reinterpret_cast<const float4*>(beta);
    float4* __restrict__ orow =
        reinterpret_cast<float4*>(out) + (size_t)row * VEC;
#pragma unroll
    for (int i = 0; i < ITERS; ++i) {
        const int idx = threadIdx.x + i * BLOCK;
        const float4 v  = xrow[idx];     // L2-resident from pass 1
        const float4 g  = g4[idx];
        const float4 bb = b4[idx];
        float4 o;
        o.x = (mbits >> (4*i + 0)) & 1u ? fmaf(g.x, (v.x - mu) * inv, bb.x) : bb.x;
        o.y = (mbits >> (4*i + 1)) & 1u ? fmaf(g.y, (v.y - mu) * inv, bb.y) : bb.y;
        o.z = (mbits >> (4*i + 2)) & 1u ? fmaf(g.z, (v.z - mu) * inv, bb.z) : bb.z;
        o.w = (mbits >> (4*i + 3)) & 1u ? fmaf(g.w, (v.w - mu) * inv, bb.w) : bb.w;
        __stcs(&orow[idx], o);           // streaming: don't pollute L2
    }
}

extern "C" void kernel_launch(void* const* d_in, const int* in_sizes, int n_in,
                              void* d_out, int out_size)
{
    const float* x     = (const float*)d_in[0];
    const float* gamma = (const float*)d_in[1];
    const float* beta  = (const float*)d_in[2];
    const int*   mask  = (const int*)d_in[3];
    float*       out   = (float*)d_out;

    const int B = in_sizes[0] / F_DIM;   // 4096
    dropnorm_kernel<<<B, BLOCK>>>(x, gamma, beta, mask, out);
}